// round 5
// baseline (speedup 1.0000x reference)
#include <cuda_runtime.h>
#include <stdint.h>

// Problem constants
#define BATCH 16
#define LQ 2048
#define LK 2048
#define DH 64

// Tiling: block = 64 q-rows x full LK, k-tiles of 64. 128 threads.
// microtile 8q x 4k: ty (0..7) -> q rows ty*8..ty*8+7, tx (0..15) -> k cols tx*4..+3.
// f32x2 packing: A (q) duplicated in smem -> (a,a) pairs; B (k) natural (b0,b1) pairs.
#define BQ 64
#define BK 64
#define NT 128

#define OUT_ELEMS  ((size_t)BATCH * LQ * DH)   // 2,097,152
#define ATTN_ELEMS ((size_t)BATCH * LQ * LK)   // 67,108,864

__device__ __forceinline__ float ex2a(float x) {
    float r; asm("ex2.approx.ftz.f32 %0, %1;" : "=f"(r) : "f"(x)); return r;
}

// Packed fp32x2 FMA (sm_100+): c.lo += a.lo*b.lo ; c.hi += a.hi*b.hi
#define FFMA2(c, a, b) asm("fma.rn.f32x2 %0, %1, %2, %0;" : "+l"(c) : "l"(a), "l"(b))

__device__ __forceinline__ unsigned long long pack_dup(float x) {
    unsigned long long r;
    unsigned u = __float_as_uint(x);
    asm("mov.b64 %0, {%1, %1};" : "=l"(r) : "r"(u));
    return r;
}

__global__ __launch_bounds__(NT, 4)
void wta_attn5_kernel(const float* __restrict__ q,
                      const float* __restrict__ k,
                      const float* __restrict__ v,
                      float* __restrict__ out,
                      int write_out, int write_attn, long long attn_off)
{
    __shared__ float qs2[DH][2 * BQ];   // 32 KB: [d][2*row] duplicated q values
    __shared__ float ks [DH][BK];       // 16 KB: [d][krow]

    const int b   = blockIdx.y;
    const int q0  = blockIdx.x * BQ;
    const int tid = threadIdx.x;
    const int tx  = tid & 15;     // k-group (4 cols)
    const int ty  = tid >> 4;     // q-group (8 rows)

    const float* qb = q + ((size_t)b * LQ + q0) * DH;
    const float* kb = k + (size_t)b * LK * DH;

    // ---- q tile (64 x 64): LDG + transposed duplicated STS.64 (conflict-free) ----
    {
        const int row = tid & 63;
        const int dcb = tid >> 6;               // 0..1
        #pragma unroll
        for (int it = 0; it < 8; it++) {
            int dc = (it * 2 + dcb) * 4;
            float4 w = *(const float4*)(qb + (size_t)row * DH + dc);
            *(unsigned long long*)&qs2[dc + 0][2 * row] = pack_dup(w.x);
            *(unsigned long long*)&qs2[dc + 1][2 * row] = pack_dup(w.y);
            *(unsigned long long*)&qs2[dc + 2][2 * row] = pack_dup(w.z);
            *(unsigned long long*)&qs2[dc + 3][2 * row] = pack_dup(w.w);
        }
    }

    // per-thread softmax state for 8 q-rows
    float m[8], sum[8];
    int   idx[8];
    #pragma unroll
    for (int i = 0; i < 8; i++) { m[i] = -1e30f; sum[i] = 0.0f; idx[i] = 0; }

    const float C = 0.18033688011112042f;   // 0.125 * log2(e)

    float4* az = 0;
    if (write_attn)
        az = (float4*)(out + attn_off + ((size_t)b * LQ + q0) * LK);

    for (int kt = 0; kt < LK; kt += BK) {
        __syncthreads();

        // ---- k tile (64 x 64): LDG + transposed STS (conflict-free) ----
        {
            const int krow = tid & 63;
            const int dcb  = tid >> 6;          // 0..1
            const float* kp = kb + (size_t)(kt + krow) * DH;
            #pragma unroll
            for (int it = 0; it < 8; it++) {
                int dc = (it * 2 + dcb) * 4;
                float4 w = *(const float4*)(kp + dc);
                ks[dc + 0][krow] = w.x; ks[dc + 1][krow] = w.y;
                ks[dc + 2][krow] = w.z; ks[dc + 3][krow] = w.w;
            }
        }

        // ---- interleaved zero-fill of attn slice (contiguous chunk per tile) ----
        if (write_attn) {
            float4* azc = az + (kt >> 6) * (BQ * BK / 4);   // 1024 float4 / tile
            #pragma unroll
            for (int j = 0; j < 8; j++)
                azc[tid + j * NT] = make_float4(0.f, 0.f, 0.f, 0.f);
        }
        __syncthreads();

        // ---- 8x4 microtile, f32x2-packed over j ----
        unsigned long long acc[8][2];
        #pragma unroll
        for (int i = 0; i < 8; i++) { acc[i][0] = 0ull; acc[i][1] = 0ull; }

        #pragma unroll 8
        for (int d = 0; d < DH; d++) {
            ulonglong2 bv = *(const ulonglong2*)&ks[d][tx * 4];   // (b0,b1) (b2,b3)
            #pragma unroll
            for (int p = 0; p < 4; p++) {
                ulonglong2 av = *(const ulonglong2*)&qs2[d][ty * 16 + p * 4];
                FFMA2(acc[2*p    ][0], av.x, bv.x);
                FFMA2(acc[2*p    ][1], av.x, bv.y);
                FFMA2(acc[2*p + 1][0], av.y, bv.x);
                FFMA2(acc[2*p + 1][1], av.y, bv.y);
            }
        }

        // ---- softmax partials: argmax on raw scores, MUFU exp ----
        const int kbase = kt + tx * 4;
        #pragma unroll
        for (int i = 0; i < 8; i++) {
            float s0 = __uint_as_float((unsigned)(acc[i][0] & 0xffffffffu));
            float s1 = __uint_as_float((unsigned)(acc[i][0] >> 32));
            float s2 = __uint_as_float((unsigned)(acc[i][1] & 0xffffffffu));
            float s3 = __uint_as_float((unsigned)(acc[i][1] >> 32));
            if (s0 > m[i]) { m[i] = s0; idx[i] = kbase + 0; }
            if (s1 > m[i]) { m[i] = s1; idx[i] = kbase + 1; }
            if (s2 > m[i]) { m[i] = s2; idx[i] = kbase + 2; }
            if (s3 > m[i]) { m[i] = s3; idx[i] = kbase + 3; }
            sum[i] += (ex2a(s0 * C) + ex2a(s1 * C)) + (ex2a(s2 * C) + ex2a(s3 * C));
        }
    }

    // ---- butterfly reduce (m, idx, sum) across the 16 lanes per q-row ----
    #pragma unroll
    for (int i = 0; i < 8; i++) {
        #pragma unroll
        for (int off = 8; off > 0; off >>= 1) {
            float om = __shfl_xor_sync(0xffffffffu, m[i],   off, 16);
            int   oi = __shfl_xor_sync(0xffffffffu, idx[i], off, 16);
            float os = __shfl_xor_sync(0xffffffffu, sum[i], off, 16);
            sum[i] += os;
            if (om > m[i] || (om == m[i] && oi < idx[i])) { m[i] = om; idx[i] = oi; }
        }
    }

    __syncthreads();   // order zero-fill stores before winner scatter

    // ---- scatter winners into attn ----
    if (write_attn && tx == 0) {
        #pragma unroll
        for (int i = 0; i < 8; i++) {
            float p = ex2a(m[i] * C) / sum[i];
            out[attn_off + ((size_t)b * LQ + q0 + ty * 8 + i) * LK + idx[i]] = p;
        }
    }

    // ---- dense output: out[b,q,:] = p * v[b, argmax, :] ----
    if (write_out) {
        #pragma unroll
        for (int i = 0; i < 8; i++) {
            float p = ex2a(m[i] * C) / sum[i];
            const float4 vv = *(const float4*)(v + ((size_t)b * LK + idx[i]) * DH + tx * 4);
            float4 o;
            o.x = p * vv.x; o.y = p * vv.y; o.z = p * vv.z; o.w = p * vv.w;
            *(float4*)(out + ((size_t)b * LQ + q0 + ty * 8 + i) * DH + tx * 4) = o;
        }
    }
}

extern "C" void kernel_launch(void* const* d_in, const int* in_sizes, int n_in,
                              void* d_out, int out_size)
{
    const float* q = (const float*)d_in[0];
    const float* k = (const float*)d_in[1];
    const float* v = (const float*)d_in[2];
    float* out = (float*)d_out;

    int wout = 0, wattn = 0;
    long long aoff = 0;
    size_t osz = (size_t)out_size;
    if (osz == OUT_ELEMS + ATTN_ELEMS) { wout = 1; wattn = 1; aoff = (long long)OUT_ELEMS; }
    else if (osz == ATTN_ELEMS)        { wattn = 1; aoff = 0; }
    else                               { wout = 1; }

    dim3 grid(LQ / BQ, BATCH);
    wta_attn5_kernel<<<grid, NT>>>(q, k, v, out, wout, wattn, aoff);
}